// round 6
// baseline (speedup 1.0000x reference)
#include <cuda_runtime.h>
#include <cuda_fp16.h>
#include <cstdint>

#define CHARS   10000
#define HIDDEN  1024
#define OUTPUT  100
#define BATCH   4096
#define MAXLEN  2048

#define K_PAD   10240
#define NPAD    128
#define NSLICE  8
#define K_SLICE (K_PAD / NSLICE)      // 1280
#define NCHUNK_MAIN (K_SLICE / 64)    // 20
#define NCHUNK_WC   (HIDDEN / 64)     // 16

// ---------------- device scratch (static; allocations are banned) --------
__device__ uint8_t g_hist[(size_t)BATCH * K_PAD];           // 42 MB (u8 exact)
__device__ __half  g_w1f[(size_t)HIDDEN * K_PAD];           // 21 MB
__device__ __half  g_w2f[(size_t)NPAD * HIDDEN];            // 256 KB
__device__ __half  g_wcf[(size_t)NPAD * K_PAD];             // 2.6 MB
__device__ float   g_part[(size_t)NSLICE * BATCH * NPAD];   // 16.8 MB
__device__ float   g_bc[OUTPUT];

// ---------------- PTX helpers (portable sm_80-class only) ----------------
__device__ __forceinline__ uint32_t smem_u32(const void* p) {
    uint32_t a;
    asm("{ .reg .u64 t; cvta.to.shared.u64 t, %1; cvt.u32.u64 %0, t; }"
        : "=r"(a) : "l"(p));
    return a;
}

__device__ __forceinline__ void cp16(uint32_t s, const void* g) {
    asm volatile("cp.async.cg.shared.global [%0], [%1], 16;" :: "r"(s), "l"(g));
}
#define CP_COMMIT() asm volatile("cp.async.commit_group;" ::: "memory")
#define CP_WAIT2()  asm volatile("cp.async.wait_group 2;"  ::: "memory")

__device__ __forceinline__ void ldsm4(uint32_t* r, uint32_t a) {
    asm volatile("ldmatrix.sync.aligned.m8n8.x4.shared.b16 {%0,%1,%2,%3}, [%4];"
        : "=r"(r[0]), "=r"(r[1]), "=r"(r[2]), "=r"(r[3]) : "r"(a));
}
__device__ __forceinline__ void ldsm4t(uint32_t* r, uint32_t a) {
    asm volatile("ldmatrix.sync.aligned.m8n8.x4.trans.shared.b16 {%0,%1,%2,%3}, [%4];"
        : "=r"(r[0]), "=r"(r[1]), "=r"(r[2]), "=r"(r[3]) : "r"(a));
}

// D(16x8,f32) += A(16x16,f16) @ B(16x8,f16)
__device__ __forceinline__ void mma_f16(float* c, const uint32_t* a, const uint32_t* b) {
    asm volatile(
        "mma.sync.aligned.m16n8k16.row.col.f32.f16.f16.f32 "
        "{%0,%1,%2,%3}, {%4,%5,%6,%7}, {%8,%9}, {%0,%1,%2,%3};"
        : "+f"(c[0]), "+f"(c[1]), "+f"(c[2]), "+f"(c[3])
        : "r"(a[0]), "r"(a[1]), "r"(a[2]), "r"(a[3]), "r"(b[0]), "r"(b[1]));
}

// u8 x4 -> two half2 words via magic number 0x6400 (=1024.0h): (1024+b) - 1024
__device__ __forceinline__ void u8x4_to_h2x2(uint32_t x, uint32_t& lo, uint32_t& hi) {
    const uint32_t K = 0x64006400u;
    uint32_t a = __byte_perm(x, 0x64646464u, 0x4140);
    uint32_t b = __byte_perm(x, 0x64646464u, 0x4342);
    __half2 ha = __hsub2(*(__half2*)&a, *(__half2*)&K);
    __half2 hb = __hsub2(*(__half2*)&b, *(__half2*)&K);
    lo = *(uint32_t*)&ha;
    hi = *(uint32_t*)&hb;
}

// smem pitch (bytes) for 64-col 16-bit rows, +8 elem pad
#define PA 144

// ---------------- kernel 1: fused prelude ---------------------------------
// blocks [0,4096): per-row histogram -> u8
// [4096,5120): conv W1 row h -> fp16 g_w1f (zero-padded to K_PAD)
// [5120,5632): conv W2 -> fp16 g_w2f (zero-padded to 128 rows)
// [5632,5645): bc = b2 + W2 @ b1
#define NB_HIST 4096
#define NB_W1   1024
#define NB_W2   512
#define NB_BC   13
#define NB_TOTAL (NB_HIST + NB_W1 + NB_W2 + NB_BC)

__global__ void __launch_bounds__(256) prelude_kernel(
        const int* __restrict__ words, const float* __restrict__ W1,
        const float* __restrict__ b1,  const float* __restrict__ W2,
        const float* __restrict__ b2) {
    __shared__ unsigned cnt[K_PAD / 2];
    const int bid = blockIdx.x, tid = threadIdx.x;

    if (bid < NB_HIST) {
        for (int i = tid; i < K_PAD / 2; i += 256) cnt[i] = 0u;
        __syncthreads();
        const int* w = words + (size_t)bid * MAXLEN;
        #pragma unroll 8
        for (int j = tid; j < MAXLEN; j += 256) {
            unsigned c = (unsigned)w[j];
            atomicAdd(&cnt[c >> 1], 1u << ((c & 1u) * 16));
        }
        __syncthreads();
        uint32_t* out = (uint32_t*)(g_hist + (size_t)bid * K_PAD);
        for (int i = tid; i < K_PAD / 4; i += 256)
            out[i] = __byte_perm(cnt[2 * i], cnt[2 * i + 1], 0x6420);
    } else if (bid < NB_HIST + NB_W1) {
        int h = bid - NB_HIST;
        const float* src = W1 + (size_t)h * CHARS;
        __half2* dst = (__half2*)(g_w1f + (size_t)h * K_PAD);
        for (int i = tid; i < K_PAD / 2; i += 256) {
            float2 v = (i < CHARS / 2) ? *(const float2*)(src + 2 * i)
                                       : make_float2(0.f, 0.f);
            dst[i] = __floats2half2_rn(v.x, v.y);
        }
    } else if (bid < NB_HIST + NB_W1 + NB_W2) {
        unsigned i = (bid - NB_HIST - NB_W1) * 256u + tid;  // over 128*1024
        unsigned o = i >> 10;
        float v = (o < OUTPUT) ? W2[(size_t)o * HIDDEN + (i & 1023u)] : 0.f;
        g_w2f[i] = __float2half_rn(v);
    } else {
        int o = (bid - NB_HIST - NB_W1 - NB_W2) * 8 + (tid >> 5);
        if (o < OUTPUT) {
            int lane = tid & 31;
            const float* w = W2 + (size_t)o * HIDDEN;
            float s = 0.f;
            #pragma unroll 8
            for (int h = lane; h < HIDDEN; h += 32) s += w[h] * b1[h];
            #pragma unroll
            for (int off = 16; off; off >>= 1)
                s += __shfl_xor_sync(0xFFFFFFFFu, s, off);
            if (lane == 0) g_bc[o] = b2[o] + s;
        }
    }
}

// ---------------- kernel 2: Wc = W2 @ W1 (fp16, pure cp.async) -----------
// CTA tile: 128 o x 64 c, K = 1024 (16 chunks of 64 h). grid 160.
// 8 warps (4m x 2n). A = g_w2f [o][h]; B = g_w1f [h][c] via trans ldmatrix.
// stage = 27648 B, 3 stages.
#define WC_A 0
#define WC_B 18432
#define WC_STG 27648

__global__ void __launch_bounds__(256, 2) wc_gemm() {
    extern __shared__ char smn[];
    uint32_t sb = smem_u32(smn);
    const int tid = threadIdx.x, lid = tid & 31, wid = tid >> 5;
    const int wm = wid >> 1, wn = wid & 1, gid = lid >> 2, t4 = lid & 3;
    const int c0 = blockIdx.x * 64;

    // A: 128 o-rows x 128B per chunk
    const int arow = tid >> 1;
    const int acol = (tid & 1) * 64;
    const char* gA = (const char*)(g_w2f + (size_t)arow * HIDDEN) + acol;
    const uint32_t sA = sb + WC_A + arow * PA + acol;
    // B: 64 h-rows x 128B (64 c fp16) per chunk
    const int brow = tid >> 2;
    const int bcol = (tid & 3) * 32;
    const char* gB = (const char*)(g_w1f + (size_t)brow * K_PAD + c0) + bcol;
    const uint32_t sB = sb + WC_B + brow * PA + bcol;

    auto issue = [&](int it, int s) {
        if (it < NCHUNK_WC) {
            uint32_t so = s * WC_STG;
            size_t ka = (size_t)it * 128;              // +64 h = 128B (A)
            size_t kb = (size_t)it * 64 * K_PAD * 2;   // +64 h-rows (B)
            #pragma unroll
            for (int i = 0; i < 4; i++) cp16(sA + so + i * 16, gA + ka + i * 16);
            #pragma unroll
            for (int i = 0; i < 2; i++) cp16(sB + so + i * 16, gB + kb + i * 16);
        }
        CP_COMMIT();
    };

    float acc[2][4][4];
    #pragma unroll
    for (int mb = 0; mb < 2; mb++)
        #pragma unroll
        for (int nf = 0; nf < 4; nf++)
            #pragma unroll
            for (int e = 0; e < 4; e++) acc[mb][nf][e] = 0.f;

    issue(0, 0); issue(1, 1); issue(2, 2);
    int sc = 0;
    for (int it = 0; it < NCHUNK_WC; ++it) {
        uint32_t st = sb + sc * WC_STG;
        CP_WAIT2();
        __syncthreads();
        #pragma unroll
        for (int ks = 0; ks < 4; ks++) {
            uint32_t a[2][4];
            #pragma unroll
            for (int mb = 0; mb < 2; mb++) {
                uint32_t r = (wm * 32 + mb * 16 + (lid & 15));
                ldsm4(a[mb], st + WC_A + r * PA + ks * 32 + (lid >> 4) * 16);
            }
            #pragma unroll
            for (int nq = 0; nq < 2; nq++) {
                uint32_t r = ks * 16 + ((lid >> 3) & 1) * 8 + (lid & 7);
                uint32_t cb = (wn * 32 + nq * 16) * 2 + ((lid >> 4) & 1) * 16;
                uint32_t b[4];
                ldsm4t(b, st + WC_B + r * PA + cb);
                #pragma unroll
                for (int mb = 0; mb < 2; mb++)
                    #pragma unroll
                    for (int f = 0; f < 2; f++)
                        mma_f16(acc[mb][nq * 2 + f], a[mb], &b[f * 2]);
            }
        }
        __syncthreads();
        issue(it + 3, sc);
        sc = (sc == 2) ? 0 : sc + 1;
    }

    // epilogue: fp16 Wc directly (no k-split, no combine)
    #pragma unroll
    for (int mb = 0; mb < 2; mb++)
        #pragma unroll
        for (int nf = 0; nf < 4; nf++) {
            int o = wm * 32 + mb * 16 + gid;
            int c = c0 + wn * 32 + nf * 8 + t4 * 2;
            *(__half2*)(g_wcf + (size_t)o * K_PAD + c) =
                __floats2half2_rn(acc[mb][nf][0], acc[mb][nf][1]);
            *(__half2*)(g_wcf + (size_t)(o + 8) * K_PAD + c) =
                __floats2half2_rn(acc[mb][nf][2], acc[mb][nf][3]);
        }
}

// ---------------- kernel 3: main GEMM  part = hist(u8) @ Wc^T ------------
// CTA: 128 m x 128 n, K-slice 1280 (20 chunks). grid (32, 8). 8 warps.
// A arrives as u8 (raw, 3 stages), converted in-smem to one fp16 tile.
// B fp16 cp.async, 3 stages.
#define MG_B    0                      // 3 x 18432
#define MG_AF   55296                  // 1 x 18432 (fp16 A tile)
#define MG_RAW  73728                  // 3 x 10240 (u8 raw, pitch 80)
#define MG_SMEM 104448

__global__ void __launch_bounds__(256, 2) main_gemm() {
    extern __shared__ char smn[];
    uint32_t sb = smem_u32(smn);
    const int tid = threadIdx.x, lid = tid & 31, wid = tid >> 5;
    const int wm = wid >> 1, wn = wid & 1, gid = lid >> 2, t4 = lid & 3;
    const int m0 = blockIdx.x * 128;
    const int kbase = blockIdx.y * K_SLICE;

    const int row = tid >> 1;              // 0..127
    const int hf  = tid & 1;
    // B: 128 n-rows x 128B per chunk
    const char* gB = (const char*)(g_wcf + (size_t)row * K_PAD + kbase) + hf * 64;
    const uint32_t sB = sb + MG_B + row * PA + hf * 64;
    // raw A: 128 m-rows x 64B per chunk (u8), pitch 80
    const char* gR = (const char*)(g_hist + (size_t)(m0 + row) * K_PAD + kbase) + hf * 32;
    const uint32_t sR = sb + MG_RAW + row * 80 + hf * 32;

    auto issue = [&](int it, int s) {
        if (it < NCHUNK_MAIN) {
            size_t kb = (size_t)it * 128;      // B: 64 fp16 = 128B
            size_t kr = (size_t)it * 64;       // raw: 64 u8
            uint32_t soB = s * 18432, soR = s * 10240;
            #pragma unroll
            for (int i = 0; i < 4; i++) cp16(sB + soB + i * 16, gB + kb + i * 16);
            #pragma unroll
            for (int i = 0; i < 2; i++) cp16(sR + soR + i * 16, gR + kr + i * 16);
        }
        CP_COMMIT();
    };

    float acc[2][8][4];
    #pragma unroll
    for (int mb = 0; mb < 2; mb++)
        #pragma unroll
        for (int nf = 0; nf < 8; nf++)
            #pragma unroll
            for (int e = 0; e < 4; e++) acc[mb][nf][e] = 0.f;

    issue(0, 0); issue(1, 1); issue(2, 2);
    int sc = 0;
    for (int it = 0; it < NCHUNK_MAIN; ++it) {
        CP_WAIT2();
        __syncthreads();
        // convert raw u8 chunk -> fp16 A tile (single buffer)
        {
            const char* rp = smn + (MG_RAW - 0) + sc * 10240 + row * 80 + hf * 32;
            uint4 r0 = *(const uint4*)rp;
            uint4 r1 = *(const uint4*)(rp + 16);
            uint32_t h[16];
            u8x4_to_h2x2(r0.x, h[0],  h[1]);
            u8x4_to_h2x2(r0.y, h[2],  h[3]);
            u8x4_to_h2x2(r0.z, h[4],  h[5]);
            u8x4_to_h2x2(r0.w, h[6],  h[7]);
            u8x4_to_h2x2(r1.x, h[8],  h[9]);
            u8x4_to_h2x2(r1.y, h[10], h[11]);
            u8x4_to_h2x2(r1.z, h[12], h[13]);
            u8x4_to_h2x2(r1.w, h[14], h[15]);
            char* ap = smn + MG_AF + row * PA + hf * 64;
            *(uint4*)(ap)      = make_uint4(h[0],  h[1],  h[2],  h[3]);
            *(uint4*)(ap + 16) = make_uint4(h[4],  h[5],  h[6],  h[7]);
            *(uint4*)(ap + 32) = make_uint4(h[8],  h[9],  h[10], h[11]);
            *(uint4*)(ap + 48) = make_uint4(h[12], h[13], h[14], h[15]);
        }
        __syncthreads();
        uint32_t stB = sb + MG_B + sc * 18432;
        uint32_t stA = sb + MG_AF;
        #pragma unroll
        for (int ks = 0; ks < 4; ks++) {
            uint32_t a[2][4];
            #pragma unroll
            for (int mb = 0; mb < 2; mb++) {
                uint32_t r = (wm * 32 + mb * 16 + (lid & 15));
                ldsm4(a[mb], stA + r * PA + ks * 32 + (lid >> 4) * 16);
            }
            #pragma unroll
            for (int nq = 0; nq < 4; nq++) {
                uint32_t r = wn * 64 + nq * 16 + ((lid >> 4) & 1) * 8 + (lid & 7);
                uint32_t ad = stB + r * PA + ks * 32 + ((lid >> 3) & 1) * 16;
                uint32_t bh[4];
                ldsm4(bh, ad);
                #pragma unroll
                for (int mb = 0; mb < 2; mb++)
                    #pragma unroll
                    for (int f = 0; f < 2; f++)
                        mma_f16(acc[mb][nq * 2 + f], a[mb], &bh[f * 2]);
            }
        }
        __syncthreads();
        issue(it + 3, sc);
        sc = (sc == 2) ? 0 : sc + 1;
    }

    float* base = g_part + (size_t)blockIdx.y * BATCH * NPAD;
    #pragma unroll
    for (int mb = 0; mb < 2; mb++)
        #pragma unroll
        for (int nf = 0; nf < 8; nf++) {
            int r = m0 + wm * 32 + mb * 16 + gid;
            int c = wn * 64 + nf * 8 + t4 * 2;
            *(float2*)(base + (size_t)r * NPAD + c) =
                make_float2(acc[mb][nf][0], acc[mb][nf][1]);
            *(float2*)(base + (size_t)(r + 8) * NPAD + c) =
                make_float2(acc[mb][nf][2], acc[mb][nf][3]);
        }
}

// ---------------- kernel 4: split-K reduce + bias ------------------------
__global__ void __launch_bounds__(256) reduce_kernel(float* __restrict__ out) {
    int i = blockIdx.x * 256 + threadIdx.x;
    int b = i / OUTPUT;
    int o = i - b * OUTPUT;
    float s = g_bc[o];
    #pragma unroll
    for (int sl = 0; sl < NSLICE; sl++)
        s += g_part[((size_t)sl * BATCH + b) * NPAD + o];
    out[i] = s;
}

// ---------------- launch ---------------------------------------------------
extern "C" void kernel_launch(void* const* d_in, const int* in_sizes, int n_in,
                              void* d_out, int out_size) {
    const int*   words = (const int*)  d_in[0];
    const float* W1    = (const float*)d_in[1];
    const float* b1    = (const float*)d_in[2];
    const float* W2    = (const float*)d_in[3];
    const float* b2    = (const float*)d_in[4];

    prelude_kernel<<<NB_TOTAL, 256>>>(words, W1, b1, W2, b2);

    cudaFuncSetAttribute(wc_gemm, cudaFuncAttributeMaxDynamicSharedMemorySize,
                         3 * WC_STG);
    wc_gemm<<<K_PAD / 64, 256, 3 * WC_STG>>>();

    cudaFuncSetAttribute(main_gemm, cudaFuncAttributeMaxDynamicSharedMemorySize,
                         MG_SMEM);
    main_gemm<<<dim3(32, NSLICE), 256, MG_SMEM>>>();

    reduce_kernel<<<(BATCH * OUTPUT) / 256, 256>>>((float*)d_out);
}